// round 2
// baseline (speedup 1.0000x reference)
#include <cuda_runtime.h>

// Problem constants (fixed by the dataset)
#define N_NODES 100000
#define N_EDGES 1600000
#define D_IN    256
#define N_HEADS 4
#define D_OUT   32
#define D_HID   128   // N_HEADS * D_OUT
#define NEG_SLOPE 0.2f

// ---------------- scratch (static __device__ globals; allocation-free) ------
__device__ float g_ft[N_NODES * D_HID];      // 51.2 MB projected features
__device__ float g_el[N_NODES * N_HEADS];    // per-node left logits
__device__ float g_er[N_NODES * N_HEADS];    // per-node right logits
__device__ float g_m [N_NODES * N_HEADS];    // segment max
__device__ float g_dn[N_NODES * N_HEADS];    // segment sum of exp
__device__ float g_ex[N_EDGES * N_HEADS];    // per-edge exp(e - m)

// ---------------- K0: init ---------------------------------------------------
__global__ void k_init(float* __restrict__ out) {
    int i = blockIdx.x * blockDim.x + threadIdx.x;
    if (i < N_NODES * D_HID) out[i] = 0.0f;
    if (i < N_NODES * N_HEADS) {
        g_m[i]  = -__int_as_float(0x7f800000);  // -inf
        g_dn[i] = 0.0f;
    }
}

// ---------------- K1: GEMM ft = x @ W^T  (M=100000, N=128, K=256) -----------
// Classic 128x128x16 tile, 256 threads, 8x8 register blocking.
__global__ __launch_bounds__(256) void k_gemm(const float* __restrict__ x,
                                              const float* __restrict__ w) {
    const int BM = 128, BN = 128, BK = 16;
    __shared__ float As[BK][BM];
    __shared__ float Bs[BK][BN];

    int tid  = threadIdx.x;
    int trow = tid >> 4;          // 0..15
    int tcol = tid & 15;          // 0..15
    int rowBase = blockIdx.x * BM;

    float acc[8][8];
#pragma unroll
    for (int i = 0; i < 8; i++)
#pragma unroll
        for (int j = 0; j < 8; j++) acc[i][j] = 0.0f;

    for (int k0 = 0; k0 < D_IN; k0 += BK) {
        // Load A tile (x): 128 rows x 16 k = 512 float4, 2 per thread
#pragma unroll
        for (int t = 0; t < 2; t++) {
            int j  = tid + t * 256;
            int r  = j >> 2;
            int kq = (j & 3) * 4;
            int grow = rowBase + r;
            float4 v = make_float4(0.f, 0.f, 0.f, 0.f);
            if (grow < N_NODES)
                v = *(const float4*)(x + (long long)grow * D_IN + k0 + kq);
            As[kq + 0][r] = v.x; As[kq + 1][r] = v.y;
            As[kq + 2][r] = v.z; As[kq + 3][r] = v.w;
        }
        // Load B tile (W, row-major [128,256], K-major like A)
#pragma unroll
        for (int t = 0; t < 2; t++) {
            int j  = tid + t * 256;
            int c  = j >> 2;
            int kq = (j & 3) * 4;
            float4 v = *(const float4*)(w + c * D_IN + k0 + kq);
            Bs[kq + 0][c] = v.x; Bs[kq + 1][c] = v.y;
            Bs[kq + 2][c] = v.z; Bs[kq + 3][c] = v.w;
        }
        __syncthreads();

#pragma unroll
        for (int k = 0; k < BK; k++) {
            float ra[8], rb[8];
#pragma unroll
            for (int i = 0; i < 8; i++) ra[i] = As[k][trow * 8 + i];
#pragma unroll
            for (int j = 0; j < 8; j++) rb[j] = Bs[k][tcol * 8 + j];
#pragma unroll
            for (int i = 0; i < 8; i++)
#pragma unroll
                for (int j = 0; j < 8; j++)
                    acc[i][j] += ra[i] * rb[j];
        }
        __syncthreads();
    }

    // Store 8x8 tile (two float4 per row)
#pragma unroll
    for (int i = 0; i < 8; i++) {
        int grow = rowBase + trow * 8 + i;
        if (grow < N_NODES) {
            float* dst = g_ft + (long long)grow * D_HID + tcol * 8;
            float4 v0 = make_float4(acc[i][0], acc[i][1], acc[i][2], acc[i][3]);
            float4 v1 = make_float4(acc[i][4], acc[i][5], acc[i][6], acc[i][7]);
            *(float4*)(dst + 0) = v0;
            *(float4*)(dst + 4) = v1;
        }
    }
}

// ---------------- K2: per-node logits el/er (warp per node) -----------------
__global__ void k_elr(const float* __restrict__ al, const float* __restrict__ ar) {
    int gw   = (blockIdx.x * blockDim.x + threadIdx.x) >> 5;
    int lane = threadIdx.x & 31;
    if (gw >= N_NODES) return;

    int h = lane >> 3;            // head: lane*4 / 32
    int j = (lane & 7) * 4;       // feature offset within head
    float4 f = *(const float4*)(g_ft + (long long)gw * D_HID + lane * 4);
    float4 a = *(const float4*)(al + h * D_OUT + j);
    float4 b = *(const float4*)(ar + h * D_OUT + j);
    float pl = f.x * a.x + f.y * a.y + f.z * a.z + f.w * a.w;
    float pr = f.x * b.x + f.y * b.y + f.z * b.z + f.w * b.w;
#pragma unroll
    for (int off = 4; off > 0; off >>= 1) {
        pl += __shfl_xor_sync(0xffffffffu, pl, off);
        pr += __shfl_xor_sync(0xffffffffu, pr, off);
    }
    if ((lane & 7) == 0) {
        g_el[gw * N_HEADS + h] = pl;
        g_er[gw * N_HEADS + h] = pr;
    }
}

// ---------------- float atomic max -------------------------------------------
__device__ __forceinline__ void atomicMaxF(float* addr, float v) {
    if (v >= 0.0f) atomicMax((int*)addr, __float_as_int(v));
    else           atomicMin((unsigned int*)addr, __float_as_uint(v));
}

__device__ __forceinline__ float lrelu(float v) {
    return v > 0.0f ? v : NEG_SLOPE * v;
}

// ---------------- K3: edge segment-max ---------------------------------------
__global__ void k_max(const int* __restrict__ src,
                      const int* __restrict__ dst) {
    int e = blockIdx.x * blockDim.x + threadIdx.x;
    if (e >= N_EDGES) return;
    int s = src[e], d = dst[e];
    if ((unsigned)s >= N_NODES || (unsigned)d >= N_NODES) return;  // defensive
    float4 el = *(const float4*)(g_el + s * N_HEADS);
    float4 er = *(const float4*)(g_er + d * N_HEADS);
    atomicMaxF(&g_m[d * N_HEADS + 0], lrelu(el.x + er.x));
    atomicMaxF(&g_m[d * N_HEADS + 1], lrelu(el.y + er.y));
    atomicMaxF(&g_m[d * N_HEADS + 2], lrelu(el.z + er.z));
    atomicMaxF(&g_m[d * N_HEADS + 3], lrelu(el.w + er.w));
}

// ---------------- K4: edge exp + segment-sum ---------------------------------
__global__ void k_exp(const int* __restrict__ src,
                      const int* __restrict__ dst) {
    int e = blockIdx.x * blockDim.x + threadIdx.x;
    if (e >= N_EDGES) return;
    int s = src[e], d = dst[e];
    if ((unsigned)s >= N_NODES || (unsigned)d >= N_NODES) return;  // defensive
    float4 el = *(const float4*)(g_el + s * N_HEADS);
    float4 er = *(const float4*)(g_er + d * N_HEADS);
    float4 m4 = *(const float4*)(g_m  + d * N_HEADS);
    float4 ex;
    ex.x = expf(lrelu(el.x + er.x) - m4.x);
    ex.y = expf(lrelu(el.y + er.y) - m4.y);
    ex.z = expf(lrelu(el.z + er.z) - m4.z);
    ex.w = expf(lrelu(el.w + er.w) - m4.w);
    *(float4*)(g_ex + (long long)e * N_HEADS) = ex;
    atomicAdd(&g_dn[d * N_HEADS + 0], ex.x);
    atomicAdd(&g_dn[d * N_HEADS + 1], ex.y);
    atomicAdd(&g_dn[d * N_HEADS + 2], ex.z);
    atomicAdd(&g_dn[d * N_HEADS + 3], ex.w);
}

// ---------------- K5: aggregation (warp per edge) -----------------------------
__global__ void k_agg(const int* __restrict__ src,
                      const int* __restrict__ dst,
                      float* __restrict__ out) {
    int gw   = (blockIdx.x * blockDim.x + threadIdx.x) >> 5;
    int lane = threadIdx.x & 31;
    if (gw >= N_EDGES) return;
    int s = src[gw], d = dst[gw];
    if ((unsigned)s >= N_NODES || (unsigned)d >= N_NODES) return;  // defensive
    float4 ex = *(const float4*)(g_ex + (long long)gw * N_HEADS);
    float4 dn = *(const float4*)(g_dn + d * N_HEADS);
    float a0 = ex.x / dn.x, a1 = ex.y / dn.y, a2 = ex.z / dn.z, a3 = ex.w / dn.w;
    const float* fs = g_ft + (long long)s * D_HID;
    float*       od = out  + (long long)d * D_HID;
    atomicAdd(od + 0  + lane, a0 * fs[0  + lane]);
    atomicAdd(od + 32 + lane, a1 * fs[32 + lane]);
    atomicAdd(od + 64 + lane, a2 * fs[64 + lane]);
    atomicAdd(od + 96 + lane, a3 * fs[96 + lane]);
}

// ---------------- launch ------------------------------------------------------
extern "C" void kernel_launch(void* const* d_in, const int* in_sizes, int n_in,
                              void* d_out, int out_size) {
    const float* x   = (const float*)d_in[0];
    const float* w   = (const float*)d_in[1];
    const float* al  = (const float*)d_in[2];
    const float* ar  = (const float*)d_in[3];
    const int*   src = (const int*)d_in[4];
    const int*   dst = (const int*)d_in[5];
    float*       out = (float*)d_out;

    k_init<<<(N_NODES * D_HID + 255) / 256, 256>>>(out);
    k_gemm<<<(N_NODES + 127) / 128, 256>>>(x, w);
    k_elr<<<(N_NODES * 32 + 255) / 256, 256>>>(al, ar);
    k_max<<<(N_EDGES + 255) / 256, 256>>>(src, dst);
    k_exp<<<(N_EDGES + 255) / 256, 256>>>(src, dst);
    k_agg<<<((long long)N_EDGES * 32 + 255) / 256, 256>>>(src, dst, out);
}

// round 4
// speedup vs baseline: 1.2014x; 1.2014x over previous
#include <cuda_runtime.h>
#include <cstdint>

// Problem constants
#define N_NODES 100000
#define N_EDGES 1600000
#define D_IN    256
#define N_HEADS 4
#define D_OUT   32
#define D_HID   128
#define NEG_SLOPE 0.2f

// ---------------- scratch (static device globals) ----------------------------
__device__ float g_ft[N_NODES * D_HID];      // 51.2 MB projected features
__device__ float g_el[N_NODES * N_HEADS];
__device__ float g_er[N_NODES * N_HEADS];
__device__ float g_dn[N_NODES * N_HEADS];
__device__ float g_ex[N_EDGES * N_HEADS];

// ---------------- K0: init ----------------------------------------------------
__global__ void k_init(float* __restrict__ out) {
    int i = blockIdx.x * blockDim.x + threadIdx.x;
    if (i < N_NODES * D_HID) out[i] = 0.0f;
    if (i < N_NODES * N_HEADS) g_dn[i] = 0.0f;
}

// ---------------- tf32 helpers --------------------------------------------------
__device__ __forceinline__ float trunc_tf32(float f) {
    return __uint_as_float(__float_as_uint(f) & 0xFFFFE000u);
}

__device__ __forceinline__ void mma_tf32_m16n8k8(float* d, const float* a, float b0, float b1) {
    asm volatile(
        "mma.sync.aligned.m16n8k8.row.col.f32.tf32.tf32.f32 "
        "{%0,%1,%2,%3}, {%4,%5,%6,%7}, {%8,%9}, {%0,%1,%2,%3};"
        : "+f"(d[0]), "+f"(d[1]), "+f"(d[2]), "+f"(d[3])
        : "r"(__float_as_uint(a[0])), "r"(__float_as_uint(a[1])),
          "r"(__float_as_uint(a[2])), "r"(__float_as_uint(a[3])),
          "r"(__float_as_uint(b0)),  "r"(__float_as_uint(b1)));
}

// SMEM layout (dynamic)
#define LDPAD 36                         // floats per row (32 + 4 pad), stride 144B (16B-aligned)
#define TILE_FLOATS (128 * LDPAD)        // 4608 floats = 18432 B
#define OFF_AH 0
#define OFF_AL (1 * TILE_FLOATS)
#define OFF_BH (2 * TILE_FLOATS)
#define OFF_BL (3 * TILE_FLOATS)
#define OFF_ALS (4 * TILE_FLOATS)        // attn_l (128 floats)
#define OFF_ARS (4 * TILE_FLOATS + 128)
#define SMEM_FLOATS (4 * TILE_FLOATS + 256)
#define SMEM_BYTES (SMEM_FLOATS * 4)

// ---------------- K1: 3xTF32 mma.sync GEMM + fused el/er epilogue ---------------
// Block: 256 threads (8 warps, 4x2). Tile: 128 rows x 128 cols. K in 32-chunks.
__global__ __launch_bounds__(256) void k_gemm_mma(const float* __restrict__ x,
                                                  const float* __restrict__ w,
                                                  const float* __restrict__ al,
                                                  const float* __restrict__ ar) {
    extern __shared__ __align__(16) float smem[];
    float* Ah = smem + OFF_AH;
    float* Al = smem + OFF_AL;
    float* Bh = smem + OFF_BH;
    float* Bl = smem + OFF_BL;
    float* al_s = smem + OFF_ALS;
    float* ar_s = smem + OFF_ARS;

    const int tid  = threadIdx.x;
    const int lane = tid & 31;
    const int warp = tid >> 5;
    const int wm   = warp >> 1;          // 0..3 (row quadrant, 32 rows)
    const int wn   = warp & 1;           // 0..1 (col half, 64 cols)
    const int ty   = lane >> 2;          // 0..7
    const int tx   = lane & 3;           // 0..3
    const int rowBase = blockIdx.x * 128;

    if (tid < 128) { al_s[tid] = al[tid]; ar_s[tid] = ar[tid]; }

    float acc[2][8][4];
#pragma unroll
    for (int mt = 0; mt < 2; mt++)
#pragma unroll
        for (int nt = 0; nt < 8; nt++)
#pragma unroll
            for (int i = 0; i < 4; i++) acc[mt][nt][i] = 0.0f;

    for (int kc = 0; kc < D_IN; kc += 32) {
        __syncthreads();
        // Load A chunk: 128 rows x 32 k, split hi/lo. 1024 float4 / 256 thr = 4 each.
#pragma unroll
        for (int t = 0; t < 4; t++) {
            int idx = t * 256 + tid;
            int row = idx >> 3;
            int kq  = (idx & 7) << 2;
            int grow = rowBase + row;
            float4 v = make_float4(0.f, 0.f, 0.f, 0.f);
            if (grow < N_NODES)
                v = *(const float4*)(x + (size_t)grow * D_IN + kc + kq);
            float4 hi, lo;
            hi.x = trunc_tf32(v.x); lo.x = v.x - hi.x;
            hi.y = trunc_tf32(v.y); lo.y = v.y - hi.y;
            hi.z = trunc_tf32(v.z); lo.z = v.z - hi.z;
            hi.w = trunc_tf32(v.w); lo.w = v.w - hi.w;
            *(float4*)(Ah + row * LDPAD + kq) = hi;
            *(float4*)(Al + row * LDPAD + kq) = lo;
        }
        // Load B chunk: 128 n-rows x 32 k (W is [128,256] row-major; B[k][n] = W[n][k])
#pragma unroll
        for (int t = 0; t < 4; t++) {
            int idx = t * 256 + tid;
            int row = idx >> 3;
            int kq  = (idx & 7) << 2;
            float4 v = *(const float4*)(w + (size_t)row * D_IN + kc + kq);
            float4 hi, lo;
            hi.x = trunc_tf32(v.x); lo.x = v.x - hi.x;
            hi.y = trunc_tf32(v.y); lo.y = v.y - hi.y;
            hi.z = trunc_tf32(v.z); lo.z = v.z - hi.z;
            hi.w = trunc_tf32(v.w); lo.w = v.w - hi.w;
            *(float4*)(Bh + row * LDPAD + kq) = hi;
            *(float4*)(Bl + row * LDPAD + kq) = lo;
        }
        __syncthreads();

#pragma unroll
        for (int ks = 0; ks < 4; ks++) {
            int koff = ks * 8;
            // A fragments (hi and lo) for 2 m-tiles
            float ah[2][4], alo[2][4];
#pragma unroll
            for (int mt = 0; mt < 2; mt++) {
                int r = wm * 32 + mt * 16 + ty;
                ah[mt][0]  = Ah[(r    ) * LDPAD + koff + tx];
                ah[mt][1]  = Ah[(r + 8) * LDPAD + koff + tx];
                ah[mt][2]  = Ah[(r    ) * LDPAD + koff + tx + 4];
                ah[mt][3]  = Ah[(r + 8) * LDPAD + koff + tx + 4];
                alo[mt][0] = Al[(r    ) * LDPAD + koff + tx];
                alo[mt][1] = Al[(r + 8) * LDPAD + koff + tx];
                alo[mt][2] = Al[(r    ) * LDPAD + koff + tx + 4];
                alo[mt][3] = Al[(r + 8) * LDPAD + koff + tx + 4];
            }
#pragma unroll
            for (int nt = 0; nt < 8; nt++) {
                int n = wn * 64 + nt * 8 + ty;
                float bh0 = Bh[n * LDPAD + koff + tx];
                float bh1 = Bh[n * LDPAD + koff + tx + 4];
                float bl0 = Bl[n * LDPAD + koff + tx];
                float bl1 = Bl[n * LDPAD + koff + tx + 4];
#pragma unroll
                for (int mt = 0; mt < 2; mt++) {
                    mma_tf32_m16n8k8(acc[mt][nt], ah[mt],  bh0, bh1);
                    mma_tf32_m16n8k8(acc[mt][nt], ah[mt],  bl0, bl1);
                    mma_tf32_m16n8k8(acc[mt][nt], alo[mt], bh0, bh1);
                }
            }
        }
    }

    // ---------------- epilogue: store ft + fused el/er ---------------------------
    // Thread owns rows (wm*32 + mt*16 + ty) and (+8), cols wn*64 + nt*8 + tx*2 + {0,1}
#pragma unroll
    for (int mt = 0; mt < 2; mt++) {
#pragma unroll
        for (int half = 0; half < 2; half++) {
            int row = rowBase + wm * 32 + mt * 16 + ty + half * 8;
            bool valid = row < N_NODES;
            float el0 = 0.f, el1 = 0.f, er0 = 0.f, er1 = 0.f;
#pragma unroll
            for (int nt = 0; nt < 8; nt++) {
                int col = wn * 64 + nt * 8 + tx * 2;
                float d0 = acc[mt][nt][half * 2 + 0];
                float d1 = acc[mt][nt][half * 2 + 1];
                if (valid)
                    *(float2*)(g_ft + (size_t)row * D_HID + col) = make_float2(d0, d1);
                float l0 = al_s[col], l1 = al_s[col + 1];
                float r0 = ar_s[col], r1 = ar_s[col + 1];
                if (nt < 4) { el0 += d0 * l0 + d1 * l1; er0 += d0 * r0 + d1 * r1; }
                else        { el1 += d0 * l0 + d1 * l1; er1 += d0 * r0 + d1 * r1; }
            }
            // quad reduce (lanes tx=0..3 share the row)
#pragma unroll
            for (int off = 1; off <= 2; off <<= 1) {
                el0 += __shfl_xor_sync(0xffffffffu, el0, off);
                el1 += __shfl_xor_sync(0xffffffffu, el1, off);
                er0 += __shfl_xor_sync(0xffffffffu, er0, off);
                er1 += __shfl_xor_sync(0xffffffffu, er1, off);
            }
            if (tx == 0 && valid) {
                int h0 = 2 * wn;
                g_el[row * N_HEADS + h0]     = el0;
                g_el[row * N_HEADS + h0 + 1] = el1;
                g_er[row * N_HEADS + h0]     = er0;
                g_er[row * N_HEADS + h0 + 1] = er1;
            }
        }
    }
}

// ---------------- leaky relu -----------------------------------------------------
__device__ __forceinline__ float lrelu(float v) { return v > 0.0f ? v : NEG_SLOPE * v; }

// ---------------- K2: edge exp + segment-sum (no max pass; shift-invariant) -------
__global__ void k_exp(const int* __restrict__ src, const int* __restrict__ dst) {
    int e = blockIdx.x * blockDim.x + threadIdx.x;
    if (e >= N_EDGES) return;
    int s = src[e], d = dst[e];
    if ((unsigned)s >= N_NODES || (unsigned)d >= N_NODES) return;
    float4 el = *(const float4*)(g_el + s * N_HEADS);
    float4 er = *(const float4*)(g_er + d * N_HEADS);
    float4 ex;
    ex.x = expf(lrelu(el.x + er.x));
    ex.y = expf(lrelu(el.y + er.y));
    ex.z = expf(lrelu(el.z + er.z));
    ex.w = expf(lrelu(el.w + er.w));
    *(float4*)(g_ex + (size_t)e * N_HEADS) = ex;
    atomicAdd(&g_dn[d * N_HEADS + 0], ex.x);
    atomicAdd(&g_dn[d * N_HEADS + 1], ex.y);
    atomicAdd(&g_dn[d * N_HEADS + 2], ex.z);
    atomicAdd(&g_dn[d * N_HEADS + 3], ex.w);
}

// ---------------- K3: aggregation (warp per edge) ----------------------------------
__global__ void k_agg(const int* __restrict__ src, const int* __restrict__ dst,
                      float* __restrict__ out) {
    int gw   = (blockIdx.x * blockDim.x + threadIdx.x) >> 5;
    int lane = threadIdx.x & 31;
    if (gw >= N_EDGES) return;
    int s = src[gw], d = dst[gw];
    if ((unsigned)s >= N_NODES || (unsigned)d >= N_NODES) return;
    float4 ex = *(const float4*)(g_ex + (size_t)gw * N_HEADS);
    float4 dn = *(const float4*)(g_dn + d * N_HEADS);
    float a0 = ex.x / dn.x, a1 = ex.y / dn.y, a2 = ex.z / dn.z, a3 = ex.w / dn.w;
    const float* fs = g_ft + (size_t)s * D_HID;
    float*       od = out  + (size_t)d * D_HID;
    atomicAdd(od + 0  + lane, a0 * fs[0  + lane]);
    atomicAdd(od + 32 + lane, a1 * fs[32 + lane]);
    atomicAdd(od + 64 + lane, a2 * fs[64 + lane]);
    atomicAdd(od + 96 + lane, a3 * fs[96 + lane]);
}

// ---------------- launch ------------------------------------------------------------
extern "C" void kernel_launch(void* const* d_in, const int* in_sizes, int n_in,
                              void* d_out, int out_size) {
    const float* x   = (const float*)d_in[0];
    const float* w   = (const float*)d_in[1];
    const float* al  = (const float*)d_in[2];
    const float* ar  = (const float*)d_in[3];
    const int*   src = (const int*)d_in[4];
    const int*   dst = (const int*)d_in[5];
    float*       out = (float*)d_out;

    static bool attr_set = false;
    if (!attr_set) {
        cudaFuncSetAttribute(k_gemm_mma, cudaFuncAttributeMaxDynamicSharedMemorySize, SMEM_BYTES);
        attr_set = true;
    }

    k_init<<<(N_NODES * D_HID + 255) / 256, 256>>>(out);
    k_gemm_mma<<<(N_NODES + 127) / 128, 256, SMEM_BYTES>>>(x, w, al, ar);
    k_exp<<<(N_EDGES + 255) / 256, 256>>>(src, dst);
    k_agg<<<((long long)N_EDGES * 32 + 255) / 256, 256>>>(src, dst, out);
}

// round 5
// speedup vs baseline: 1.3882x; 1.1554x over previous
#include <cuda_runtime.h>
#include <cstdint>

#define N_NODES 100000
#define N_EDGES 1600000
#define D_IN    256
#define N_HEADS 4
#define D_OUT   32
#define D_HID   128
#define NEG_SLOPE 0.2f

#define SCAN_B 512
#define NB ((N_NODES + SCAN_B - 1) / SCAN_B)   // 196

// ---------------- scratch (static device globals) ----------------------------
__device__ float g_ft[N_NODES * D_HID];      // 51.2 MB projected features
__device__ float g_el[N_NODES * N_HEADS];
__device__ float g_er[N_NODES * N_HEADS];
__device__ int   g_cnt[N_NODES];
__device__ int   g_scan[N_NODES];
__device__ int   g_off[N_NODES];
__device__ int   g_cursor[N_NODES];
__device__ int   g_btot[256];
__device__ int   g_boff[256];
__device__ uint4 g_rec[2 * N_EDGES];         // 32B per edge: {ex0..ex3, src, pad}

// ---------------- K: zero histogram -------------------------------------------
__global__ void k_zero() {
    int i = blockIdx.x * blockDim.x + threadIdx.x;
    if (i < N_NODES) g_cnt[i] = 0;
}

// ---------------- K: histogram of dst ------------------------------------------
__global__ void k_hist(const int* __restrict__ dst) {
    int e = blockIdx.x * blockDim.x + threadIdx.x;
    if (e >= N_EDGES) return;
    int d = dst[e];
    if ((unsigned)d < N_NODES) atomicAdd(&g_cnt[d], 1);
}

// ---------------- K: scan stage 1 (per-block inclusive) -------------------------
__global__ __launch_bounds__(SCAN_B) void k_scan1() {
    __shared__ int sh[SCAN_B];
    int i = blockIdx.x * SCAN_B + threadIdx.x;
    int v = (i < N_NODES) ? g_cnt[i] : 0;
    sh[threadIdx.x] = v;
    __syncthreads();
#pragma unroll
    for (int off = 1; off < SCAN_B; off <<= 1) {
        int t = (threadIdx.x >= off) ? sh[threadIdx.x - off] : 0;
        __syncthreads();
        sh[threadIdx.x] += t;
        __syncthreads();
    }
    if (i < N_NODES) g_scan[i] = sh[threadIdx.x];
    if (threadIdx.x == SCAN_B - 1) g_btot[blockIdx.x] = sh[SCAN_B - 1];
}

// ---------------- K: scan stage 2 (block totals, exclusive) ---------------------
__global__ __launch_bounds__(256) void k_scan2() {
    __shared__ int sh[256];
    int tid = threadIdx.x;
    int v = (tid < NB) ? g_btot[tid] : 0;
    sh[tid] = v;
    __syncthreads();
#pragma unroll
    for (int off = 1; off < 256; off <<= 1) {
        int t = (tid >= off) ? sh[tid - off] : 0;
        __syncthreads();
        sh[tid] += t;
        __syncthreads();
    }
    if (tid < NB) g_boff[tid] = sh[tid] - v;
}

// ---------------- K: scan stage 3 (write exclusive offsets) ---------------------
__global__ __launch_bounds__(SCAN_B) void k_scan3() {
    int i = blockIdx.x * SCAN_B + threadIdx.x;
    if (i < N_NODES) {
        int off = g_scan[i] - g_cnt[i] + g_boff[blockIdx.x];
        g_off[i]    = off;
        g_cursor[i] = off;
    }
}

// ---------------- tf32 helpers --------------------------------------------------
__device__ __forceinline__ float trunc_tf32(float f) {
    return __uint_as_float(__float_as_uint(f) & 0xFFFFE000u);
}

__device__ __forceinline__ void mma_tf32_m16n8k8(float* d, const float* a, float b0, float b1) {
    asm volatile(
        "mma.sync.aligned.m16n8k8.row.col.f32.tf32.tf32.f32 "
        "{%0,%1,%2,%3}, {%4,%5,%6,%7}, {%8,%9}, {%0,%1,%2,%3};"
        : "+f"(d[0]), "+f"(d[1]), "+f"(d[2]), "+f"(d[3])
        : "r"(__float_as_uint(a[0])), "r"(__float_as_uint(a[1])),
          "r"(__float_as_uint(a[2])), "r"(__float_as_uint(a[3])),
          "r"(__float_as_uint(b0)),  "r"(__float_as_uint(b1)));
}

#define LDPAD 36
#define TILE_FLOATS (128 * LDPAD)
#define OFF_AH 0
#define OFF_AL (1 * TILE_FLOATS)
#define OFF_BH (2 * TILE_FLOATS)
#define OFF_BL (3 * TILE_FLOATS)
#define OFF_ALS (4 * TILE_FLOATS)
#define OFF_ARS (4 * TILE_FLOATS + 128)
#define SMEM_FLOATS (4 * TILE_FLOATS + 256)
#define SMEM_BYTES (SMEM_FLOATS * 4)

// ---------------- K: 3xTF32 mma.sync GEMM + fused el/er epilogue ----------------
__global__ __launch_bounds__(256) void k_gemm_mma(const float* __restrict__ x,
                                                  const float* __restrict__ w,
                                                  const float* __restrict__ al,
                                                  const float* __restrict__ ar) {
    extern __shared__ __align__(16) float smem[];
    float* Ah = smem + OFF_AH;
    float* Al = smem + OFF_AL;
    float* Bh = smem + OFF_BH;
    float* Bl = smem + OFF_BL;
    float* al_s = smem + OFF_ALS;
    float* ar_s = smem + OFF_ARS;

    const int tid  = threadIdx.x;
    const int lane = tid & 31;
    const int warp = tid >> 5;
    const int wm   = warp >> 1;
    const int wn   = warp & 1;
    const int ty   = lane >> 2;
    const int tx   = lane & 3;
    const int rowBase = blockIdx.x * 128;

    if (tid < 128) { al_s[tid] = al[tid]; ar_s[tid] = ar[tid]; }

    float acc[2][8][4];
#pragma unroll
    for (int mt = 0; mt < 2; mt++)
#pragma unroll
        for (int nt = 0; nt < 8; nt++)
#pragma unroll
            for (int i = 0; i < 4; i++) acc[mt][nt][i] = 0.0f;

    for (int kc = 0; kc < D_IN; kc += 32) {
        __syncthreads();
#pragma unroll
        for (int t = 0; t < 4; t++) {
            int idx = t * 256 + tid;
            int row = idx >> 3;
            int kq  = (idx & 7) << 2;
            int grow = rowBase + row;
            float4 v = make_float4(0.f, 0.f, 0.f, 0.f);
            if (grow < N_NODES)
                v = *(const float4*)(x + (size_t)grow * D_IN + kc + kq);
            float4 hi, lo;
            hi.x = trunc_tf32(v.x); lo.x = v.x - hi.x;
            hi.y = trunc_tf32(v.y); lo.y = v.y - hi.y;
            hi.z = trunc_tf32(v.z); lo.z = v.z - hi.z;
            hi.w = trunc_tf32(v.w); lo.w = v.w - hi.w;
            *(float4*)(Ah + row * LDPAD + kq) = hi;
            *(float4*)(Al + row * LDPAD + kq) = lo;
        }
#pragma unroll
        for (int t = 0; t < 4; t++) {
            int idx = t * 256 + tid;
            int row = idx >> 3;
            int kq  = (idx & 7) << 2;
            float4 v = *(const float4*)(w + (size_t)row * D_IN + kc + kq);
            float4 hi, lo;
            hi.x = trunc_tf32(v.x); lo.x = v.x - hi.x;
            hi.y = trunc_tf32(v.y); lo.y = v.y - hi.y;
            hi.z = trunc_tf32(v.z); lo.z = v.z - hi.z;
            hi.w = trunc_tf32(v.w); lo.w = v.w - hi.w;
            *(float4*)(Bh + row * LDPAD + kq) = hi;
            *(float4*)(Bl + row * LDPAD + kq) = lo;
        }
        __syncthreads();

#pragma unroll
        for (int ks = 0; ks < 4; ks++) {
            int koff = ks * 8;
            float ah[2][4], alo[2][4];
#pragma unroll
            for (int mt = 0; mt < 2; mt++) {
                int r = wm * 32 + mt * 16 + ty;
                ah[mt][0]  = Ah[(r    ) * LDPAD + koff + tx];
                ah[mt][1]  = Ah[(r + 8) * LDPAD + koff + tx];
                ah[mt][2]  = Ah[(r    ) * LDPAD + koff + tx + 4];
                ah[mt][3]  = Ah[(r + 8) * LDPAD + koff + tx + 4];
                alo[mt][0] = Al[(r    ) * LDPAD + koff + tx];
                alo[mt][1] = Al[(r + 8) * LDPAD + koff + tx];
                alo[mt][2] = Al[(r    ) * LDPAD + koff + tx + 4];
                alo[mt][3] = Al[(r + 8) * LDPAD + koff + tx + 4];
            }
#pragma unroll
            for (int nt = 0; nt < 8; nt++) {
                int n = wn * 64 + nt * 8 + ty;
                float bh0 = Bh[n * LDPAD + koff + tx];
                float bh1 = Bh[n * LDPAD + koff + tx + 4];
                float bl0 = Bl[n * LDPAD + koff + tx];
                float bl1 = Bl[n * LDPAD + koff + tx + 4];
#pragma unroll
                for (int mt = 0; mt < 2; mt++) {
                    mma_tf32_m16n8k8(acc[mt][nt], ah[mt],  bh0, bh1);
                    mma_tf32_m16n8k8(acc[mt][nt], ah[mt],  bl0, bl1);
                    mma_tf32_m16n8k8(acc[mt][nt], alo[mt], bh0, bh1);
                }
            }
        }
    }

#pragma unroll
    for (int mt = 0; mt < 2; mt++) {
#pragma unroll
        for (int half = 0; half < 2; half++) {
            int row = rowBase + wm * 32 + mt * 16 + ty + half * 8;
            bool valid = row < N_NODES;
            float el0 = 0.f, el1 = 0.f, er0 = 0.f, er1 = 0.f;
#pragma unroll
            for (int nt = 0; nt < 8; nt++) {
                int col = wn * 64 + nt * 8 + tx * 2;
                float d0 = acc[mt][nt][half * 2 + 0];
                float d1 = acc[mt][nt][half * 2 + 1];
                if (valid)
                    *(float2*)(g_ft + (size_t)row * D_HID + col) = make_float2(d0, d1);
                float l0 = al_s[col], l1 = al_s[col + 1];
                float r0 = ar_s[col], r1 = ar_s[col + 1];
                if (nt < 4) { el0 += d0 * l0 + d1 * l1; er0 += d0 * r0 + d1 * r1; }
                else        { el1 += d0 * l0 + d1 * l1; er1 += d0 * r0 + d1 * r1; }
            }
#pragma unroll
            for (int off = 1; off <= 2; off <<= 1) {
                el0 += __shfl_xor_sync(0xffffffffu, el0, off);
                el1 += __shfl_xor_sync(0xffffffffu, el1, off);
                er0 += __shfl_xor_sync(0xffffffffu, er0, off);
                er1 += __shfl_xor_sync(0xffffffffu, er1, off);
            }
            if (tx == 0 && valid) {
                int h0 = 2 * wn;
                g_el[row * N_HEADS + h0]     = el0;
                g_el[row * N_HEADS + h0 + 1] = el1;
                g_er[row * N_HEADS + h0]     = er0;
                g_er[row * N_HEADS + h0 + 1] = er1;
            }
        }
    }
}

__device__ __forceinline__ float lrelu(float v) { return v > 0.0f ? v : NEG_SLOPE * v; }

// ---------------- K: scatter edges into dst-sorted records ----------------------
__global__ void k_scatter(const int* __restrict__ src, const int* __restrict__ dst) {
    int e = blockIdx.x * blockDim.x + threadIdx.x;
    if (e >= N_EDGES) return;
    int s = src[e], d = dst[e];
    if ((unsigned)s >= N_NODES || (unsigned)d >= N_NODES) return;
    int pos = atomicAdd(&g_cursor[d], 1);
    float4 el = *(const float4*)(g_el + s * N_HEADS);
    float4 er = *(const float4*)(g_er + d * N_HEADS);
    float4 ex;
    ex.x = expf(lrelu(el.x + er.x));
    ex.y = expf(lrelu(el.y + er.y));
    ex.z = expf(lrelu(el.z + er.z));
    ex.w = expf(lrelu(el.w + er.w));
    uint4* r = g_rec + 2 * (size_t)pos;
    *(float4*)r = ex;
    r[1] = make_uint4((unsigned)s, 0u, 0u, 0u);
}

// ---------------- K: per-node segmented aggregation (warp per node) -------------
__global__ __launch_bounds__(256) void k_agg2(float* __restrict__ out) {
    int gw   = (blockIdx.x * blockDim.x + threadIdx.x) >> 5;
    int lane = threadIdx.x & 31;
    if (gw >= N_NODES) return;
    int cnt   = g_cnt[gw];
    int start = g_off[gw];

    float acc0 = 0.f, acc1 = 0.f, acc2 = 0.f, acc3 = 0.f;
    float dn0 = 0.f, dn1 = 0.f, dn2 = 0.f, dn3 = 0.f;

    const uint4* rec = g_rec + 2 * (size_t)start;
    int i = 0;
    for (; i + 2 <= cnt; i += 2) {
        float4 exA = *(const float4*)(rec + 2 * i);
        int    sA  = (int)(rec + 2 * i)[1].x;
        float4 exB = *(const float4*)(rec + 2 * (i + 1));
        int    sB  = (int)(rec + 2 * (i + 1))[1].x;
        const float* fA = g_ft + (size_t)sA * D_HID;
        const float* fB = g_ft + (size_t)sB * D_HID;
        float a0 = fA[lane], a1 = fA[32 + lane], a2 = fA[64 + lane], a3 = fA[96 + lane];
        float b0 = fB[lane], b1 = fB[32 + lane], b2 = fB[64 + lane], b3 = fB[96 + lane];
        acc0 += exA.x * a0 + exB.x * b0;
        acc1 += exA.y * a1 + exB.y * b1;
        acc2 += exA.z * a2 + exB.z * b2;
        acc3 += exA.w * a3 + exB.w * b3;
        dn0 += exA.x + exB.x; dn1 += exA.y + exB.y;
        dn2 += exA.z + exB.z; dn3 += exA.w + exB.w;
    }
    if (i < cnt) {
        float4 ex = *(const float4*)(rec + 2 * i);
        int    s  = (int)(rec + 2 * i)[1].x;
        const float* f = g_ft + (size_t)s * D_HID;
        acc0 += ex.x * f[lane];
        acc1 += ex.y * f[32 + lane];
        acc2 += ex.z * f[64 + lane];
        acc3 += ex.w * f[96 + lane];
        dn0 += ex.x; dn1 += ex.y; dn2 += ex.z; dn3 += ex.w;
    }

    float* o = out + (size_t)gw * D_HID;
    o[lane]      = cnt ? acc0 / dn0 : 0.f;
    o[32 + lane] = cnt ? acc1 / dn1 : 0.f;
    o[64 + lane] = cnt ? acc2 / dn2 : 0.f;
    o[96 + lane] = cnt ? acc3 / dn3 : 0.f;
}

// ---------------- launch ----------------------------------------------------------
extern "C" void kernel_launch(void* const* d_in, const int* in_sizes, int n_in,
                              void* d_out, int out_size) {
    const float* x   = (const float*)d_in[0];
    const float* w   = (const float*)d_in[1];
    const float* al  = (const float*)d_in[2];
    const float* ar  = (const float*)d_in[3];
    const int*   src = (const int*)d_in[4];
    const int*   dst = (const int*)d_in[5];
    float*       out = (float*)d_out;

    static bool attr_set = false;
    if (!attr_set) {
        cudaFuncSetAttribute(k_gemm_mma, cudaFuncAttributeMaxDynamicSharedMemorySize, SMEM_BYTES);
        attr_set = true;
    }

    k_zero<<<(N_NODES + 255) / 256, 256>>>();
    k_hist<<<(N_EDGES + 255) / 256, 256>>>(dst);
    k_scan1<<<NB, SCAN_B>>>();
    k_scan2<<<1, 256>>>();
    k_scan3<<<NB, SCAN_B>>>();
    k_gemm_mma<<<(N_NODES + 127) / 128, 256, SMEM_BYTES>>>(x, w, al, ar);
    k_scatter<<<(N_EDGES + 255) / 256, 256>>>(src, dst);
    k_agg2<<<(N_NODES * 32 + 255) / 256, 256>>>(out);
}

// round 6
// speedup vs baseline: 2.1150x; 1.5235x over previous
#include <cuda_runtime.h>
#include <cstdint>

#define N_NODES 100000
#define N_EDGES 1600000
#define D_IN    256
#define N_HEADS 4
#define D_OUT   32
#define D_HID   128
#define NEG_SLOPE 0.2f

#define SCAN_B 512
#define NB ((N_NODES + SCAN_B - 1) / SCAN_B)   // 196

// ---------------- scratch (static device globals) ----------------------------
__device__ float  g_ft[N_NODES * D_HID];
__device__ float  g_el[N_NODES * N_HEADS];
__device__ float  g_er[N_NODES * N_HEADS];
__device__ int    g_cnt[N_NODES];
__device__ int    g_scan[N_NODES];
__device__ int    g_off[N_NODES];
__device__ int    g_cursor[N_NODES];
__device__ int    g_btot[256];
__device__ int    g_boff[256];
__device__ float4 g_exv[N_EDGES];            // dst-sorted exp values (16B/edge)
__device__ int    g_srcv[N_EDGES];           // dst-sorted src index  (4B/edge)

// ---------------- K: histogram of dst ------------------------------------------
__global__ void k_hist(const int* __restrict__ dst) {
    int e = blockIdx.x * blockDim.x + threadIdx.x;
    if (e >= N_EDGES) return;
    int d = dst[e];
    if ((unsigned)d < N_NODES) atomicAdd(&g_cnt[d], 1);
}

// ---------------- K: scan stage 1 (per-block inclusive) -------------------------
__global__ __launch_bounds__(SCAN_B) void k_scan1() {
    __shared__ int sh[SCAN_B];
    int i = blockIdx.x * SCAN_B + threadIdx.x;
    int v = (i < N_NODES) ? g_cnt[i] : 0;
    sh[threadIdx.x] = v;
    __syncthreads();
#pragma unroll
    for (int off = 1; off < SCAN_B; off <<= 1) {
        int t = (threadIdx.x >= off) ? sh[threadIdx.x - off] : 0;
        __syncthreads();
        sh[threadIdx.x] += t;
        __syncthreads();
    }
    if (i < N_NODES) g_scan[i] = sh[threadIdx.x];
    if (threadIdx.x == SCAN_B - 1) g_btot[blockIdx.x] = sh[SCAN_B - 1];
}

// ---------------- K: scan stage 2 ------------------------------------------------
__global__ __launch_bounds__(256) void k_scan2() {
    __shared__ int sh[256];
    int tid = threadIdx.x;
    int v = (tid < NB) ? g_btot[tid] : 0;
    sh[tid] = v;
    __syncthreads();
#pragma unroll
    for (int off = 1; off < 256; off <<= 1) {
        int t = (tid >= off) ? sh[tid - off] : 0;
        __syncthreads();
        sh[tid] += t;
        __syncthreads();
    }
    if (tid < NB) g_boff[tid] = sh[tid] - v;
}

// ---------------- K: scan stage 3 -------------------------------------------------
__global__ __launch_bounds__(SCAN_B) void k_scan3() {
    int i = blockIdx.x * SCAN_B + threadIdx.x;
    if (i < N_NODES) {
        int off = g_scan[i] - g_cnt[i] + g_boff[blockIdx.x];
        g_off[i]    = off;
        g_cursor[i] = off;
    }
}

// ---------------- tf32 / cp.async helpers -----------------------------------------
__device__ __forceinline__ float trunc_tf32(float f) {
    return __uint_as_float(__float_as_uint(f) & 0xFFFFE000u);
}
__device__ __forceinline__ uint32_t smem_u32(const void* p) {
    uint32_t a;
    asm("{ .reg .u64 t; cvta.to.shared.u64 t, %1; cvt.u32.u64 %0, t; }" : "=r"(a) : "l"(p));
    return a;
}
__device__ __forceinline__ void cp16(void* sdst, const void* gsrc, int zfill) {
    asm volatile("cp.async.cg.shared.global [%0], [%1], 16, %2;"
                 :: "r"(smem_u32(sdst)), "l"(gsrc), "r"(zfill));
}
#define CP_COMMIT() asm volatile("cp.async.commit_group;" ::: "memory")
#define CP_WAIT(n)  asm volatile("cp.async.wait_group %0;" :: "n"(n) : "memory")

__device__ __forceinline__ void mma_tf32_m16n8k8(float* d, const float* a, float b0, float b1) {
    asm volatile(
        "mma.sync.aligned.m16n8k8.row.col.f32.tf32.tf32.f32 "
        "{%0,%1,%2,%3}, {%4,%5,%6,%7}, {%8,%9}, {%0,%1,%2,%3};"
        : "+f"(d[0]), "+f"(d[1]), "+f"(d[2]), "+f"(d[3])
        : "r"(__float_as_uint(a[0])), "r"(__float_as_uint(a[1])),
          "r"(__float_as_uint(a[2])), "r"(__float_as_uint(a[3])),
          "r"(__float_as_uint(b0)),  "r"(__float_as_uint(b1)));
}

#define LDPAD 36
#define TILE_FLOATS (128 * LDPAD)
#define OFF_A(b) ((b) * TILE_FLOATS)
#define OFF_B(b) ((2 + (b)) * TILE_FLOATS)
#define OFF_ALS  (4 * TILE_FLOATS)
#define OFF_ARS  (4 * TILE_FLOATS + 128)
#define SMEM_FLOATS (4 * TILE_FLOATS + 256)
#define SMEM_BYTES (SMEM_FLOATS * 4)

// ---------------- K: cp.async double-buffered 3xTF32 GEMM + fused el/er -----------
__global__ __launch_bounds__(256) void k_gemm_mma(const float* __restrict__ x,
                                                  const float* __restrict__ w,
                                                  const float* __restrict__ al,
                                                  const float* __restrict__ ar) {
    extern __shared__ __align__(16) float smem[];
    float* al_s = smem + OFF_ALS;
    float* ar_s = smem + OFF_ARS;

    const int tid  = threadIdx.x;
    const int lane = tid & 31;
    const int warp = tid >> 5;
    const int wm   = warp >> 1;
    const int wn   = warp & 1;
    const int ty   = lane >> 2;
    const int tx   = lane & 3;
    const int rowBase = blockIdx.x * 128;

    if (tid < 128) { al_s[tid] = al[tid]; ar_s[tid] = ar[tid]; }

    float acc[2][8][4];
#pragma unroll
    for (int mt = 0; mt < 2; mt++)
#pragma unroll
        for (int nt = 0; nt < 8; nt++)
#pragma unroll
            for (int i = 0; i < 4; i++) acc[mt][nt][i] = 0.0f;

    // prefetch of chunk c into buffer b
    auto prefetch = [&](int c, int b) {
#pragma unroll
        for (int t = 0; t < 4; t++) {
            int j   = t * 256 + tid;
            int row = j >> 3;
            int kq  = (j & 7) << 2;
            int grow = rowBase + row;
            cp16(smem + OFF_A(b) + row * LDPAD + kq,
                 x + (size_t)grow * D_IN + c * 32 + kq,
                 grow < N_NODES ? 16 : 0);
        }
#pragma unroll
        for (int t = 0; t < 4; t++) {
            int j   = t * 256 + tid;
            int row = j >> 3;
            int kq  = (j & 7) << 2;
            cp16(smem + OFF_B(b) + row * LDPAD + kq,
                 w + (size_t)row * D_IN + c * 32 + kq, 16);
        }
        CP_COMMIT();
    };

    prefetch(0, 0);
#pragma unroll
    for (int c = 0; c < 8; c++) {
        int buf = c & 1;
        if (c + 1 < 8) { prefetch(c + 1, (c + 1) & 1); CP_WAIT(1); }
        else           { CP_WAIT(0); }
        __syncthreads();

        const float* A = smem + OFF_A(buf);
        const float* B = smem + OFF_B(buf);
#pragma unroll
        for (int ks = 0; ks < 4; ks++) {
            int koff = ks * 8;
            float ah[2][4], alo[2][4];
#pragma unroll
            for (int mt = 0; mt < 2; mt++) {
                int r = wm * 32 + mt * 16 + ty;
                float a0 = A[(r    ) * LDPAD + koff + tx];
                float a1 = A[(r + 8) * LDPAD + koff + tx];
                float a2 = A[(r    ) * LDPAD + koff + tx + 4];
                float a3 = A[(r + 8) * LDPAD + koff + tx + 4];
                ah[mt][0] = trunc_tf32(a0); alo[mt][0] = a0 - ah[mt][0];
                ah[mt][1] = trunc_tf32(a1); alo[mt][1] = a1 - ah[mt][1];
                ah[mt][2] = trunc_tf32(a2); alo[mt][2] = a2 - ah[mt][2];
                ah[mt][3] = trunc_tf32(a3); alo[mt][3] = a3 - ah[mt][3];
            }
#pragma unroll
            for (int nt = 0; nt < 8; nt++) {
                int n = wn * 64 + nt * 8 + ty;
                float b0 = B[n * LDPAD + koff + tx];
                float b1 = B[n * LDPAD + koff + tx + 4];
                float bh0 = trunc_tf32(b0), bl0 = b0 - bh0;
                float bh1 = trunc_tf32(b1), bl1 = b1 - bh1;
#pragma unroll
                for (int mt = 0; mt < 2; mt++) {
                    mma_tf32_m16n8k8(acc[mt][nt], ah[mt],  bh0, bh1);
                    mma_tf32_m16n8k8(acc[mt][nt], ah[mt],  bl0, bl1);
                    mma_tf32_m16n8k8(acc[mt][nt], alo[mt], bh0, bh1);
                }
            }
        }
        __syncthreads();
    }

    // epilogue: store ft + fused el/er (quad reduce)
#pragma unroll
    for (int mt = 0; mt < 2; mt++) {
#pragma unroll
        for (int half = 0; half < 2; half++) {
            int row = rowBase + wm * 32 + mt * 16 + ty + half * 8;
            bool valid = row < N_NODES;
            float el0 = 0.f, el1 = 0.f, er0 = 0.f, er1 = 0.f;
#pragma unroll
            for (int nt = 0; nt < 8; nt++) {
                int col = wn * 64 + nt * 8 + tx * 2;
                float d0 = acc[mt][nt][half * 2 + 0];
                float d1 = acc[mt][nt][half * 2 + 1];
                if (valid)
                    *(float2*)(g_ft + (size_t)row * D_HID + col) = make_float2(d0, d1);
                float l0 = al_s[col], l1 = al_s[col + 1];
                float r0 = ar_s[col], r1 = ar_s[col + 1];
                if (nt < 4) { el0 += d0 * l0 + d1 * l1; er0 += d0 * r0 + d1 * r1; }
                else        { el1 += d0 * l0 + d1 * l1; er1 += d0 * r0 + d1 * r1; }
            }
#pragma unroll
            for (int off = 1; off <= 2; off <<= 1) {
                el0 += __shfl_xor_sync(0xffffffffu, el0, off);
                el1 += __shfl_xor_sync(0xffffffffu, el1, off);
                er0 += __shfl_xor_sync(0xffffffffu, er0, off);
                er1 += __shfl_xor_sync(0xffffffffu, er1, off);
            }
            if (tx == 0 && valid) {
                int h0 = 2 * wn;
                g_el[row * N_HEADS + h0]     = el0;
                g_el[row * N_HEADS + h0 + 1] = el1;
                g_er[row * N_HEADS + h0]     = er0;
                g_er[row * N_HEADS + h0 + 1] = er1;
            }
        }
    }
}

__device__ __forceinline__ float lrelu(float v) { return v > 0.0f ? v : NEG_SLOPE * v; }

// ---------------- K: scatter edges into dst-sorted split arrays -------------------
__global__ void k_scatter(const int* __restrict__ src, const int* __restrict__ dst) {
    int e = blockIdx.x * blockDim.x + threadIdx.x;
    if (e >= N_EDGES) return;
    int s = src[e], d = dst[e];
    if ((unsigned)s >= N_NODES || (unsigned)d >= N_NODES) return;
    int pos = atomicAdd(&g_cursor[d], 1);
    float4 el = *(const float4*)(g_el + s * N_HEADS);
    float4 er = *(const float4*)(g_er + d * N_HEADS);
    float4 ex;
    ex.x = expf(lrelu(el.x + er.x));
    ex.y = expf(lrelu(el.y + er.y));
    ex.z = expf(lrelu(el.z + er.z));
    ex.w = expf(lrelu(el.w + er.w));
    g_exv[pos]  = ex;
    g_srcv[pos] = s;
}

// ---------------- K: per-node aggregation (warp per node, MLP-16 unroll) -----------
__global__ __launch_bounds__(256) void k_agg2(float* __restrict__ out) {
    int gw   = (blockIdx.x * blockDim.x + threadIdx.x) >> 5;
    int lane = threadIdx.x & 31;
    if (gw >= N_NODES) return;
    int cnt   = g_cnt[gw];
    int start = g_off[gw];

    float acc0 = 0.f, acc1 = 0.f, acc2 = 0.f, acc3 = 0.f;
    float dn0 = 0.f, dn1 = 0.f, dn2 = 0.f, dn3 = 0.f;

    const float4* exA  = g_exv + start;
    const int*    srcA = g_srcv + start;

    int i = 0;
    for (; i + 4 <= cnt; i += 4) {
        // warp-uniform broadcast loads
        int s0 = srcA[i], s1 = srcA[i + 1], s2 = srcA[i + 2], s3 = srcA[i + 3];
        float4 e0 = exA[i], e1 = exA[i + 1], e2 = exA[i + 2], e3 = exA[i + 3];
        const float* f0 = g_ft + (size_t)s0 * D_HID;
        const float* f1 = g_ft + (size_t)s1 * D_HID;
        const float* f2 = g_ft + (size_t)s2 * D_HID;
        const float* f3 = g_ft + (size_t)s3 * D_HID;
        // 16 independent loads
        float v00 = f0[lane], v01 = f0[32 + lane], v02 = f0[64 + lane], v03 = f0[96 + lane];
        float v10 = f1[lane], v11 = f1[32 + lane], v12 = f1[64 + lane], v13 = f1[96 + lane];
        float v20 = f2[lane], v21 = f2[32 + lane], v22 = f2[64 + lane], v23 = f2[96 + lane];
        float v30 = f3[lane], v31 = f3[32 + lane], v32 = f3[64 + lane], v33 = f3[96 + lane];
        acc0 += e0.x * v00 + e1.x * v10 + e2.x * v20 + e3.x * v30;
        acc1 += e0.y * v01 + e1.y * v11 + e2.y * v21 + e3.y * v31;
        acc2 += e0.z * v02 + e1.z * v12 + e2.z * v22 + e3.z * v32;
        acc3 += e0.w * v03 + e1.w * v13 + e2.w * v23 + e3.w * v33;
        dn0 += e0.x + e1.x + e2.x + e3.x;
        dn1 += e0.y + e1.y + e2.y + e3.y;
        dn2 += e0.z + e1.z + e2.z + e3.z;
        dn3 += e0.w + e1.w + e2.w + e3.w;
    }
    for (; i < cnt; i++) {
        int s = srcA[i];
        float4 ex = exA[i];
        const float* f = g_ft + (size_t)s * D_HID;
        acc0 += ex.x * f[lane];
        acc1 += ex.y * f[32 + lane];
        acc2 += ex.z * f[64 + lane];
        acc3 += ex.w * f[96 + lane];
        dn0 += ex.x; dn1 += ex.y; dn2 += ex.z; dn3 += ex.w;
    }

    float* o = out + (size_t)gw * D_HID;
    o[lane]      = cnt ? acc0 / dn0 : 0.f;
    o[32 + lane] = cnt ? acc1 / dn1 : 0.f;
    o[64 + lane] = cnt ? acc2 / dn2 : 0.f;
    o[96 + lane] = cnt ? acc3 / dn3 : 0.f;
}

// ---------------- launch -------------------------------------------------------------
extern "C" void kernel_launch(void* const* d_in, const int* in_sizes, int n_in,
                              void* d_out, int out_size) {
    const float* x   = (const float*)d_in[0];
    const float* w   = (const float*)d_in[1];
    const float* al  = (const float*)d_in[2];
    const float* ar  = (const float*)d_in[3];
    const int*   src = (const int*)d_in[4];
    const int*   dst = (const int*)d_in[5];
    float*       out = (float*)d_out;

    static bool init_done = false;
    static cudaStream_t s2;
    static cudaEvent_t evFork, evJoin;
    static void* cntAddr = nullptr;
    if (!init_done) {
        cudaFuncSetAttribute(k_gemm_mma, cudaFuncAttributeMaxDynamicSharedMemorySize, SMEM_BYTES);
        cudaStreamCreateWithFlags(&s2, cudaStreamNonBlocking);
        cudaEventCreateWithFlags(&evFork, cudaEventDisableTiming);
        cudaEventCreateWithFlags(&evJoin, cudaEventDisableTiming);
        cudaGetSymbolAddress(&cntAddr, g_cnt);
        init_done = true;
    }

    // fork: histogram + scan chain on s2, GEMM on main stream
    cudaEventRecord(evFork, 0);
    cudaStreamWaitEvent(s2, evFork, 0);
    cudaMemsetAsync(cntAddr, 0, N_NODES * sizeof(int), s2);
    k_hist<<<(N_EDGES + 255) / 256, 256, 0, s2>>>(dst);
    k_scan1<<<NB, SCAN_B, 0, s2>>>();
    k_scan2<<<1, 256, 0, s2>>>();
    k_scan3<<<NB, SCAN_B, 0, s2>>>();
    cudaEventRecord(evJoin, s2);

    k_gemm_mma<<<(N_NODES + 127) / 128, 256, SMEM_BYTES>>>(x, w, al, ar);

    // join: scatter needs scan3 (offsets) + gemm (el/er)
    cudaStreamWaitEvent(0, evJoin, 0);
    k_scatter<<<(N_EDGES + 255) / 256, 256>>>(src, dst);
    k_agg2<<<(N_NODES * 32 + 255) / 256, 256>>>(out);
}

// round 7
// speedup vs baseline: 2.7776x; 1.3133x over previous
#include <cuda_runtime.h>
#include <cstdint>

#define N_NODES 100000
#define N_EDGES 1600000
#define D_IN    256
#define N_HEADS 4
#define D_OUT   32
#define D_HID   128
#define NEG_SLOPE 0.2f

#define SCAN_B 512
#define NB ((N_NODES + SCAN_B - 1) / SCAN_B)   // 196

// ---------------- scratch (static device globals) ----------------------------
__device__ float  g_ft[N_NODES * D_HID];
__device__ float  g_el[N_NODES * N_HEADS];
__device__ float  g_er[N_NODES * N_HEADS];
__device__ int    g_cnt[N_NODES];
__device__ int    g_scan[N_NODES];
__device__ int    g_off[N_NODES];
__device__ int    g_cursor[N_NODES];
__device__ int    g_btot[256];
__device__ int    g_boff[256];
__device__ int    g_srcv[N_EDGES];           // dst-sorted src index (4B/edge)

// ---------------- K: histogram of dst ------------------------------------------
__global__ void k_hist(const int* __restrict__ dst) {
    int e = blockIdx.x * blockDim.x + threadIdx.x;
    if (e >= N_EDGES) return;
    int d = dst[e];
    if ((unsigned)d < N_NODES) atomicAdd(&g_cnt[d], 1);
}

// ---------------- K: scan stage 1 (per-block inclusive) -------------------------
__global__ __launch_bounds__(SCAN_B) void k_scan1() {
    __shared__ int sh[SCAN_B];
    int i = blockIdx.x * SCAN_B + threadIdx.x;
    int v = (i < N_NODES) ? g_cnt[i] : 0;
    sh[threadIdx.x] = v;
    __syncthreads();
#pragma unroll
    for (int off = 1; off < SCAN_B; off <<= 1) {
        int t = (threadIdx.x >= off) ? sh[threadIdx.x - off] : 0;
        __syncthreads();
        sh[threadIdx.x] += t;
        __syncthreads();
    }
    if (i < N_NODES) g_scan[i] = sh[threadIdx.x];
    if (threadIdx.x == SCAN_B - 1) g_btot[blockIdx.x] = sh[SCAN_B - 1];
}

// ---------------- K: scan stage 2 ------------------------------------------------
__global__ __launch_bounds__(256) void k_scan2() {
    __shared__ int sh[256];
    int tid = threadIdx.x;
    int v = (tid < NB) ? g_btot[tid] : 0;
    sh[tid] = v;
    __syncthreads();
#pragma unroll
    for (int off = 1; off < 256; off <<= 1) {
        int t = (tid >= off) ? sh[tid - off] : 0;
        __syncthreads();
        sh[tid] += t;
        __syncthreads();
    }
    if (tid < NB) g_boff[tid] = sh[tid] - v;
}

// ---------------- K: scan stage 3 -------------------------------------------------
__global__ __launch_bounds__(SCAN_B) void k_scan3() {
    int i = blockIdx.x * SCAN_B + threadIdx.x;
    if (i < N_NODES) {
        int off = g_scan[i] - g_cnt[i] + g_boff[blockIdx.x];
        g_off[i]    = off;
        g_cursor[i] = off;
    }
}

// ---------------- K: scatter (src-only; depends only on the scan) -----------------
__global__ void k_scatter(const int* __restrict__ src, const int* __restrict__ dst) {
    int e = blockIdx.x * blockDim.x + threadIdx.x;
    if (e >= N_EDGES) return;
    int s = src[e], d = dst[e];
    if ((unsigned)s >= N_NODES || (unsigned)d >= N_NODES) return;
    int pos = atomicAdd(&g_cursor[d], 1);
    g_srcv[pos] = s;
}

// ---------------- tf32 / cp.async helpers -----------------------------------------
__device__ __forceinline__ float trunc_tf32(float f) {
    return __uint_as_float(__float_as_uint(f) & 0xFFFFE000u);
}
__device__ __forceinline__ uint32_t smem_u32(const void* p) {
    uint32_t a;
    asm("{ .reg .u64 t; cvta.to.shared.u64 t, %1; cvt.u32.u64 %0, t; }" : "=r"(a) : "l"(p));
    return a;
}
__device__ __forceinline__ void cp16(void* sdst, const void* gsrc, int zfill) {
    asm volatile("cp.async.cg.shared.global [%0], [%1], 16, %2;"
                 :: "r"(smem_u32(sdst)), "l"(gsrc), "r"(zfill));
}
#define CP_COMMIT() asm volatile("cp.async.commit_group;" ::: "memory")
#define CP_WAIT(n)  asm volatile("cp.async.wait_group %0;" :: "n"(n) : "memory")

__device__ __forceinline__ void mma_tf32_m16n8k8(float* d, const float* a, float b0, float b1) {
    asm volatile(
        "mma.sync.aligned.m16n8k8.row.col.f32.tf32.tf32.f32 "
        "{%0,%1,%2,%3}, {%4,%5,%6,%7}, {%8,%9}, {%0,%1,%2,%3};"
        : "+f"(d[0]), "+f"(d[1]), "+f"(d[2]), "+f"(d[3])
        : "r"(__float_as_uint(a[0])), "r"(__float_as_uint(a[1])),
          "r"(__float_as_uint(a[2])), "r"(__float_as_uint(a[3])),
          "r"(__float_as_uint(b0)),  "r"(__float_as_uint(b1)));
}

#define LDPAD 36
#define TILE_FLOATS (128 * LDPAD)
#define OFF_A(b) ((b) * TILE_FLOATS)
#define OFF_B(b) ((2 + (b)) * TILE_FLOATS)
#define OFF_ALS  (4 * TILE_FLOATS)
#define OFF_ARS  (4 * TILE_FLOATS + 128)
#define SMEM_FLOATS (4 * TILE_FLOATS + 256)
#define SMEM_BYTES (SMEM_FLOATS * 4)

// ---------------- K: cp.async double-buffered 3xTF32 GEMM + fused el/er -----------
__global__ __launch_bounds__(256) void k_gemm_mma(const float* __restrict__ x,
                                                  const float* __restrict__ w,
                                                  const float* __restrict__ al,
                                                  const float* __restrict__ ar) {
    extern __shared__ __align__(16) float smem[];
    float* al_s = smem + OFF_ALS;
    float* ar_s = smem + OFF_ARS;

    const int tid  = threadIdx.x;
    const int lane = tid & 31;
    const int warp = tid >> 5;
    const int wm   = warp >> 1;
    const int wn   = warp & 1;
    const int ty   = lane >> 2;
    const int tx   = lane & 3;
    const int rowBase = blockIdx.x * 128;

    if (tid < 128) { al_s[tid] = al[tid]; ar_s[tid] = ar[tid]; }

    float acc[2][8][4];
#pragma unroll
    for (int mt = 0; mt < 2; mt++)
#pragma unroll
        for (int nt = 0; nt < 8; nt++)
#pragma unroll
            for (int i = 0; i < 4; i++) acc[mt][nt][i] = 0.0f;

    auto prefetch = [&](int c, int b) {
#pragma unroll
        for (int t = 0; t < 4; t++) {
            int j   = t * 256 + tid;
            int row = j >> 3;
            int kq  = (j & 7) << 2;
            int grow = rowBase + row;
            cp16(smem + OFF_A(b) + row * LDPAD + kq,
                 x + (size_t)grow * D_IN + c * 32 + kq,
                 grow < N_NODES ? 16 : 0);
        }
#pragma unroll
        for (int t = 0; t < 4; t++) {
            int j   = t * 256 + tid;
            int row = j >> 3;
            int kq  = (j & 7) << 2;
            cp16(smem + OFF_B(b) + row * LDPAD + kq,
                 w + (size_t)row * D_IN + c * 32 + kq, 16);
        }
        CP_COMMIT();
    };

    prefetch(0, 0);
#pragma unroll
    for (int c = 0; c < 8; c++) {
        int buf = c & 1;
        if (c + 1 < 8) { prefetch(c + 1, (c + 1) & 1); CP_WAIT(1); }
        else           { CP_WAIT(0); }
        __syncthreads();

        const float* A = smem + OFF_A(buf);
        const float* B = smem + OFF_B(buf);
#pragma unroll
        for (int ks = 0; ks < 4; ks++) {
            int koff = ks * 8;
            float ah[2][4], alo[2][4];
#pragma unroll
            for (int mt = 0; mt < 2; mt++) {
                int r = wm * 32 + mt * 16 + ty;
                float a0 = A[(r    ) * LDPAD + koff + tx];
                float a1 = A[(r + 8) * LDPAD + koff + tx];
                float a2 = A[(r    ) * LDPAD + koff + tx + 4];
                float a3 = A[(r + 8) * LDPAD + koff + tx + 4];
                ah[mt][0] = trunc_tf32(a0); alo[mt][0] = a0 - ah[mt][0];
                ah[mt][1] = trunc_tf32(a1); alo[mt][1] = a1 - ah[mt][1];
                ah[mt][2] = trunc_tf32(a2); alo[mt][2] = a2 - ah[mt][2];
                ah[mt][3] = trunc_tf32(a3); alo[mt][3] = a3 - ah[mt][3];
            }
#pragma unroll
            for (int nt = 0; nt < 8; nt++) {
                int n = wn * 64 + nt * 8 + ty;
                float b0 = B[n * LDPAD + koff + tx];
                float b1 = B[n * LDPAD + koff + tx + 4];
                float bh0 = trunc_tf32(b0), bl0 = b0 - bh0;
                float bh1 = trunc_tf32(b1), bl1 = b1 - bh1;
#pragma unroll
                for (int mt = 0; mt < 2; mt++) {
                    mma_tf32_m16n8k8(acc[mt][nt], ah[mt],  bh0, bh1);
                    mma_tf32_m16n8k8(acc[mt][nt], ah[mt],  bl0, bl1);
                    mma_tf32_m16n8k8(acc[mt][nt], alo[mt], bh0, bh1);
                }
            }
        }
        __syncthreads();
    }

    // epilogue: store ft + fused el/er (quad reduce)
#pragma unroll
    for (int mt = 0; mt < 2; mt++) {
#pragma unroll
        for (int half = 0; half < 2; half++) {
            int row = rowBase + wm * 32 + mt * 16 + ty + half * 8;
            bool valid = row < N_NODES;
            float el0 = 0.f, el1 = 0.f, er0 = 0.f, er1 = 0.f;
#pragma unroll
            for (int nt = 0; nt < 8; nt++) {
                int col = wn * 64 + nt * 8 + tx * 2;
                float d0 = acc[mt][nt][half * 2 + 0];
                float d1 = acc[mt][nt][half * 2 + 1];
                if (valid)
                    *(float2*)(g_ft + (size_t)row * D_HID + col) = make_float2(d0, d1);
                float l0 = al_s[col], l1 = al_s[col + 1];
                float r0 = ar_s[col], r1 = ar_s[col + 1];
                if (nt < 4) { el0 += d0 * l0 + d1 * l1; er0 += d0 * r0 + d1 * r1; }
                else        { el1 += d0 * l0 + d1 * l1; er1 += d0 * r0 + d1 * r1; }
            }
#pragma unroll
            for (int off = 1; off <= 2; off <<= 1) {
                el0 += __shfl_xor_sync(0xffffffffu, el0, off);
                el1 += __shfl_xor_sync(0xffffffffu, el1, off);
                er0 += __shfl_xor_sync(0xffffffffu, er0, off);
                er1 += __shfl_xor_sync(0xffffffffu, er1, off);
            }
            if (tx == 0 && valid) {
                int h0 = 2 * wn;
                g_el[row * N_HEADS + h0]     = el0;
                g_el[row * N_HEADS + h0 + 1] = el1;
                g_er[row * N_HEADS + h0]     = er0;
                g_er[row * N_HEADS + h0 + 1] = er1;
            }
        }
    }
}

__device__ __forceinline__ float lrelu(float v) { return v > 0.0f ? v : NEG_SLOPE * v; }

// ---------------- K: aggregation (warp/node, lane-per-4-features, inline exp) ------
__global__ __launch_bounds__(256) void k_agg2(float* __restrict__ out) {
    int gw   = (blockIdx.x * blockDim.x + threadIdx.x) >> 5;
    int lane = threadIdx.x & 31;
    if (gw >= N_NODES) return;
    int cnt   = g_cnt[gw];
    int start = g_off[gw];
    int hsel  = lane >> 3;                       // head owned by this lane

    float er_u = g_er[gw * N_HEADS + hsel];      // uniform per lane-group

    float4 acc = make_float4(0.f, 0.f, 0.f, 0.f);
    float  dn  = 0.f;

    const int* srcA = g_srcv + start;

    int i = 0;
    for (; i + 4 <= cnt; i += 4) {
        int s0 = srcA[i], s1 = srcA[i + 1], s2 = srcA[i + 2], s3 = srcA[i + 3];
        float ex0 = expf(lrelu(g_el[s0 * N_HEADS + hsel] + er_u));
        float ex1 = expf(lrelu(g_el[s1 * N_HEADS + hsel] + er_u));
        float ex2 = expf(lrelu(g_el[s2 * N_HEADS + hsel] + er_u));
        float ex3 = expf(lrelu(g_el[s3 * N_HEADS + hsel] + er_u));
        float4 f0 = *(const float4*)(g_ft + (size_t)s0 * D_HID + lane * 4);
        float4 f1 = *(const float4*)(g_ft + (size_t)s1 * D_HID + lane * 4);
        float4 f2 = *(const float4*)(g_ft + (size_t)s2 * D_HID + lane * 4);
        float4 f3 = *(const float4*)(g_ft + (size_t)s3 * D_HID + lane * 4);
        acc.x += ex0 * f0.x + ex1 * f1.x + ex2 * f2.x + ex3 * f3.x;
        acc.y += ex0 * f0.y + ex1 * f1.y + ex2 * f2.y + ex3 * f3.y;
        acc.z += ex0 * f0.z + ex1 * f1.z + ex2 * f2.z + ex3 * f3.z;
        acc.w += ex0 * f0.w + ex1 * f1.w + ex2 * f2.w + ex3 * f3.w;
        dn    += ex0 + ex1 + ex2 + ex3;
    }
    for (; i < cnt; i++) {
        int s = srcA[i];
        float ex = expf(lrelu(g_el[s * N_HEADS + hsel] + er_u));
        float4 f = *(const float4*)(g_ft + (size_t)s * D_HID + lane * 4);
        acc.x += ex * f.x; acc.y += ex * f.y;
        acc.z += ex * f.z; acc.w += ex * f.w;
        dn += ex;
    }

    float4 o;
    if (cnt) {
        o.x = acc.x / dn; o.y = acc.y / dn;
        o.z = acc.z / dn; o.w = acc.w / dn;
    } else {
        o = make_float4(0.f, 0.f, 0.f, 0.f);
    }
    *(float4*)(out + (size_t)gw * D_HID + lane * 4) = o;
}

// ---------------- launch -------------------------------------------------------------
extern "C" void kernel_launch(void* const* d_in, const int* in_sizes, int n_in,
                              void* d_out, int out_size) {
    const float* x   = (const float*)d_in[0];
    const float* w   = (const float*)d_in[1];
    const float* al  = (const float*)d_in[2];
    const float* ar  = (const float*)d_in[3];
    const int*   src = (const int*)d_in[4];
    const int*   dst = (const int*)d_in[5];
    float*       out = (float*)d_out;

    static bool init_done = false;
    static cudaStream_t s2;
    static cudaEvent_t evFork, evJoin;
    static void* cntAddr = nullptr;
    if (!init_done) {
        cudaFuncSetAttribute(k_gemm_mma, cudaFuncAttributeMaxDynamicSharedMemorySize, SMEM_BYTES);
        cudaStreamCreateWithFlags(&s2, cudaStreamNonBlocking);
        cudaEventCreateWithFlags(&evFork, cudaEventDisableTiming);
        cudaEventCreateWithFlags(&evJoin, cudaEventDisableTiming);
        cudaGetSymbolAddress(&cntAddr, g_cnt);
        init_done = true;
    }

    // fork: entire edge-indexing chain (hist, scan, scatter) runs on s2,
    // fully independent of the GEMM on the main stream.
    cudaEventRecord(evFork, 0);
    cudaStreamWaitEvent(s2, evFork, 0);
    cudaMemsetAsync(cntAddr, 0, N_NODES * sizeof(int), s2);
    k_hist<<<(N_EDGES + 255) / 256, 256, 0, s2>>>(dst);
    k_scan1<<<NB, SCAN_B, 0, s2>>>();
    k_scan2<<<1, 256, 0, s2>>>();
    k_scan3<<<NB, SCAN_B, 0, s2>>>();
    k_scatter<<<(N_EDGES + 255) / 256, 256, 0, s2>>>(src, dst);
    cudaEventRecord(evJoin, s2);

    k_gemm_mma<<<(N_NODES + 127) / 128, 256, SMEM_BYTES>>>(x, w, al, ar);

    // join: agg2 needs srcv/cnt/off (s2) + ft/el/er (GEMM)
    cudaStreamWaitEvent(0, evJoin, 0);
    k_agg2<<<(N_NODES * 32 + 255) / 256, 256>>>(out);
}